// round 1
// baseline (speedup 1.0000x reference)
#include <cuda_runtime.h>

#define B_ 16
#define T_ 2048
#define J_ 128
#define D_ 1024

#define N_ATT1 (B_*T_*J_)            // 4194304
#define OFF_ATT2 N_ATT1
#define N_ATT2 (B_*T_)               // 32768
#define OFF_G (OFF_ATT2 + N_ATT2)    // 4227072

#define SCOL 132
#define HST  36
#define SMEM1 ((64*SCOL + 128*SCOL + 128 + 64) * 4)   // 102144 bytes

__device__ float g_colterm[B_*J_];
__device__ float g_rowmax[B_*T_];
__device__ float g_agg2[B_*D_];

__device__ __forceinline__ unsigned f2tf32(float x){
    unsigned y; asm("cvt.rna.tf32.f32 %0, %1;" : "=r"(y) : "f"(x)); return y;
}

__device__ __forceinline__ void mma_tf32(float c[4], unsigned a0, unsigned a1, unsigned a2, unsigned a3,
                                         unsigned b0, unsigned b1){
    asm volatile("mma.sync.aligned.m16n8k8.row.col.f32.tf32.tf32.f32 "
        "{%0,%1,%2,%3}, {%4,%5,%6,%7}, {%8,%9}, {%0,%1,%2,%3};"
        : "+f"(c[0]), "+f"(c[1]), "+f"(c[2]), "+f"(c[3])
        : "r"(a0), "r"(a1), "r"(a2), "r"(a3), "r"(b0), "r"(b1));
}

// -------- K0: colterm[b,j] = U[b,j]·w2 + bias --------
__global__ void colterm_kernel(const float* __restrict__ U, const float* __restrict__ w,
                               const float* __restrict__ bias){
    int pair = blockIdx.x * 8 + (threadIdx.x >> 5);
    int lane = threadIdx.x & 31;
    const float* u  = U + (size_t)pair * D_;
    const float* w2 = w + D_;
    float s = 0.f;
    for (int k = lane; k < D_; k += 32) s += u[k] * w2[k];
    #pragma unroll
    for (int o = 16; o; o >>= 1) s += __shfl_xor_sync(0xffffffffu, s, o);
    if (lane == 0) g_colterm[pair] = s + bias[0];
}

// -------- K1: fused scores(tf32 mma) + softmax + agg1(tf32 mma) --------
__global__ __launch_bounds__(256, 2)
void fused1_kernel(const float* __restrict__ H, const float* __restrict__ U,
                   const float* __restrict__ w, float* __restrict__ out){
    extern __shared__ char smem_raw[];
    float*    att1sm = (float*)smem_raw;                          // 64 x 132
    unsigned* dyn    = (unsigned*)(smem_raw + 64*SCOL*4);         // 128 x 132 (phase C: Uc)
    unsigned* Hc     = dyn;                                       // 64 x 36  (phase A)
    unsigned* Vc     = dyn + 64*HST;                              // 128 x 36 (phase A)
    unsigned* Uc     = dyn;
    float*    cts    = (float*)(smem_raw + (64*SCOL + 128*SCOL)*4); // 128
    float*    hrow   = cts + 128;                                 // 64

    int tid  = threadIdx.x;
    int b    = blockIdx.y;
    int t0   = blockIdx.x * 64;
    int warp = tid >> 5, lane = tid & 31;
    int wm = warp >> 2, wn = warp & 3;
    int gid = lane >> 2, tig = lane & 3;

    if (tid < 128) cts[tid] = g_colterm[b*J_ + tid];

    const float* Hb = H + (size_t)(b*T_ + t0) * D_;
    const float* Ub = U + (size_t)b * J_ * D_;
    const float* w3 = w + 2*D_;
    float* Gb = out + OFF_G + (size_t)(b*T_ + t0) * 4096;

    float cacc[2][4][4];
    #pragma unroll
    for (int i = 0; i < 2; i++)
        #pragma unroll
        for (int j = 0; j < 4; j++)
            #pragma unroll
            for (int k = 0; k < 4; k++) cacc[i][j][k] = 0.f;

    float hp = 0.f;
    int hrow_r = tid >> 2, hpart = tid & 3;

    // ---- Phase A: S = (H .* w3) @ U^T, K = 1024 in chunks of 32; fused H@w1; G1 = H copy ----
    for (int kc = 0; kc < D_; kc += 32) {
        #pragma unroll
        for (int i = 0; i < 2; i++) {                 // H tile 64x32
            int idx = tid + i*256;
            int r = idx >> 3, c4 = (idx & 7) * 4;
            float4 h4 = *(const float4*)(Hb + (size_t)r*D_ + kc + c4);
            *(float4*)(Gb + (size_t)r*4096 + kc + c4) = h4;      // exact H copy into G[:, :D]
            uint4 u; u.x = f2tf32(h4.x); u.y = f2tf32(h4.y); u.z = f2tf32(h4.z); u.w = f2tf32(h4.w);
            *(uint4*)(Hc + r*HST + c4) = u;
        }
        #pragma unroll
        for (int i = 0; i < 4; i++) {                 // V = U .* w3 tile 128x32
            int idx = tid + i*256;
            int r = idx >> 3, c4 = (idx & 7) * 4;
            float4 u4 = *(const float4*)(Ub + (size_t)r*D_ + kc + c4);
            float4 w4 = *(const float4*)(w3 + kc + c4);
            uint4 v; v.x = f2tf32(u4.x*w4.x); v.y = f2tf32(u4.y*w4.y);
            v.z = f2tf32(u4.z*w4.z); v.w = f2tf32(u4.w*w4.w);
            *(uint4*)(Vc + r*HST + c4) = v;
        }
        __syncthreads();

        {   // H @ w1 partials (4 threads per row, 8 cols each)
            const float* w1c = w + kc + hpart*8;
            const unsigned* hc = Hc + hrow_r*HST + hpart*8;
            #pragma unroll
            for (int c = 0; c < 8; c++) hp += __uint_as_float(hc[c]) * w1c[c];
        }

        #pragma unroll
        for (int kt = 0; kt < 4; kt++) {
            unsigned bq0[4], bq1[4];
            #pragma unroll
            for (int nt = 0; nt < 4; nt++) {
                int j = wn*32 + nt*8 + gid;
                bq0[nt] = Vc[j*HST + kt*8 + tig];
                bq1[nt] = Vc[j*HST + kt*8 + 4 + tig];
            }
            #pragma unroll
            for (int mt = 0; mt < 2; mt++) {
                int r = wm*32 + mt*16 + gid;
                unsigned a0 = Hc[r*HST + kt*8 + tig];
                unsigned a1 = Hc[(r+8)*HST + kt*8 + tig];
                unsigned a2 = Hc[r*HST + kt*8 + 4 + tig];
                unsigned a3 = Hc[(r+8)*HST + kt*8 + 4 + tig];
                #pragma unroll
                for (int nt = 0; nt < 4; nt++) mma_tf32(cacc[mt][nt], a0, a1, a2, a3, bq0[nt], bq1[nt]);
            }
        }
        __syncthreads();
    }

    hp += __shfl_xor_sync(0xffffffffu, hp, 1);
    hp += __shfl_xor_sync(0xffffffffu, hp, 2);
    if (hpart == 0) hrow[hrow_r] = hp;

    // scores (minus row-constant h1+: cancels in softmax over j) -> smem
    #pragma unroll
    for (int mt = 0; mt < 2; mt++) {
        int r = wm*32 + mt*16 + gid;
        #pragma unroll
        for (int nt = 0; nt < 4; nt++) {
            int col = wn*32 + nt*8 + 2*tig;
            att1sm[r*SCOL + col]         = cacc[mt][nt][0] + cts[col];
            att1sm[r*SCOL + col + 1]     = cacc[mt][nt][1] + cts[col+1];
            att1sm[(r+8)*SCOL + col]     = cacc[mt][nt][2] + cts[col];
            att1sm[(r+8)*SCOL + col + 1] = cacc[mt][nt][3] + cts[col+1];
        }
    }
    __syncthreads();

    // ---- softmax over j (warp w owns rows w*8..w*8+7) ----
    float* att1out = out + (size_t)(b*T_ + t0) * J_;
    #pragma unroll
    for (int rr = 0; rr < 8; rr++) {
        int r = warp*8 + rr;
        float v0 = att1sm[r*SCOL + lane];
        float v1 = att1sm[r*SCOL + lane + 32];
        float v2 = att1sm[r*SCOL + lane + 64];
        float v3 = att1sm[r*SCOL + lane + 96];
        float mx = fmaxf(fmaxf(v0, v1), fmaxf(v2, v3));
        #pragma unroll
        for (int o = 16; o; o >>= 1) mx = fmaxf(mx, __shfl_xor_sync(0xffffffffu, mx, o));
        float e0 = __expf(v0 - mx), e1 = __expf(v1 - mx), e2 = __expf(v2 - mx), e3 = __expf(v3 - mx);
        float s = e0 + e1 + e2 + e3;
        #pragma unroll
        for (int o = 16; o; o >>= 1) s += __shfl_xor_sync(0xffffffffu, s, o);
        float inv = 1.f / s;
        e0 *= inv; e1 *= inv; e2 *= inv; e3 *= inv;
        att1out[(size_t)r*J_ + lane]      = e0;
        att1out[(size_t)r*J_ + lane + 32] = e1;
        att1out[(size_t)r*J_ + lane + 64] = e2;
        att1out[(size_t)r*J_ + lane + 96] = e3;
        att1sm[r*SCOL + lane]      = __uint_as_float(f2tf32(e0));   // stage tf32 att1 for GEMM2
        att1sm[r*SCOL + lane + 32] = __uint_as_float(f2tf32(e1));
        att1sm[r*SCOL + lane + 64] = __uint_as_float(f2tf32(e2));
        att1sm[r*SCOL + lane + 96] = __uint_as_float(f2tf32(e3));
        if (lane == 0) g_rowmax[b*T_ + t0 + r] = mx + hrow[r];      // full-score rowmax (bias in cts)
    }
    __syncthreads();

    // ---- Phase C: agg1 = att1 @ U (K = 128), d in chunks of 128; write G2 = agg1, G3 = H.*agg1 ----
    for (int dc = 0; dc < D_; dc += 128) {
        #pragma unroll
        for (int i = 0; i < 16; i++) {
            int idx = tid + i*256;
            int r = idx >> 5, c4 = (idx & 31) * 4;
            float4 u4 = *(const float4*)(Ub + (size_t)r*D_ + dc + c4);
            uint4 v; v.x = f2tf32(u4.x); v.y = f2tf32(u4.y); v.z = f2tf32(u4.z); v.w = f2tf32(u4.w);
            *(uint4*)(Uc + r*SCOL + c4) = v;
        }
        __syncthreads();

        float acc[2][4][4];
        #pragma unroll
        for (int i = 0; i < 2; i++)
            #pragma unroll
            for (int j = 0; j < 4; j++)
                #pragma unroll
                for (int k = 0; k < 4; k++) acc[i][j][k] = 0.f;

        #pragma unroll
        for (int kt = 0; kt < 16; kt++) {
            unsigned bq0[4], bq1[4];
            #pragma unroll
            for (int nt = 0; nt < 4; nt++) {
                int n = wn*32 + nt*8 + gid;
                bq0[nt] = Uc[(kt*8 + tig)*SCOL + n];
                bq1[nt] = Uc[(kt*8 + 4 + tig)*SCOL + n];
            }
            #pragma unroll
            for (int mt = 0; mt < 2; mt++) {
                int r = wm*32 + mt*16 + gid;
                unsigned a0 = __float_as_uint(att1sm[r*SCOL + kt*8 + tig]);
                unsigned a1 = __float_as_uint(att1sm[(r+8)*SCOL + kt*8 + tig]);
                unsigned a2 = __float_as_uint(att1sm[r*SCOL + kt*8 + 4 + tig]);
                unsigned a3 = __float_as_uint(att1sm[(r+8)*SCOL + kt*8 + 4 + tig]);
                #pragma unroll
                for (int nt = 0; nt < 4; nt++) mma_tf32(acc[mt][nt], a0, a1, a2, a3, bq0[nt], bq1[nt]);
            }
        }

        #pragma unroll
        for (int mt = 0; mt < 2; mt++) {
            #pragma unroll
            for (int nt = 0; nt < 4; nt++) {
                int r   = wm*32 + mt*16 + gid;
                int col = dc + wn*32 + nt*8 + 2*tig;
                float2 ha = *(const float2*)(Hb + (size_t)r*D_ + col);
                float2 hb = *(const float2*)(Hb + (size_t)(r+8)*D_ + col);
                float* g1 = Gb + (size_t)r*4096;
                float* g2 = Gb + (size_t)(r+8)*4096;
                *(float2*)(g1 + 1024 + col) = make_float2(acc[mt][nt][0], acc[mt][nt][1]);
                *(float2*)(g1 + 2048 + col) = make_float2(acc[mt][nt][0]*ha.x, acc[mt][nt][1]*ha.y);
                *(float2*)(g2 + 1024 + col) = make_float2(acc[mt][nt][2], acc[mt][nt][3]);
                *(float2*)(g2 + 2048 + col) = make_float2(acc[mt][nt][2]*hb.x, acc[mt][nt][3]*hb.y);
            }
        }
        __syncthreads();
    }
}

// -------- K2: att2[b,:] = softmax_t(rowmax[b,:]) --------
__global__ void att2_kernel(float* __restrict__ out){
    __shared__ float red[8];
    int b = blockIdx.x, tid = threadIdx.x;
    float v[8];
    #pragma unroll
    for (int i = 0; i < 8; i++) v[i] = g_rowmax[b*T_ + tid + i*256];
    float mx = v[0];
    #pragma unroll
    for (int i = 1; i < 8; i++) mx = fmaxf(mx, v[i]);
    #pragma unroll
    for (int o = 16; o; o >>= 1) mx = fmaxf(mx, __shfl_xor_sync(0xffffffffu, mx, o));
    if ((tid & 31) == 0) red[tid >> 5] = mx;
    __syncthreads();
    mx = red[0];
    #pragma unroll
    for (int i = 1; i < 8; i++) mx = fmaxf(mx, red[i]);
    float e[8], s = 0.f;
    #pragma unroll
    for (int i = 0; i < 8; i++) { e[i] = __expf(v[i] - mx); s += e[i]; }
    #pragma unroll
    for (int o = 16; o; o >>= 1) s += __shfl_xor_sync(0xffffffffu, s, o);
    __syncthreads();
    if ((tid & 31) == 0) red[tid >> 5] = s;
    __syncthreads();
    s = 0.f;
    #pragma unroll
    for (int i = 0; i < 8; i++) s += red[i];
    float inv = 1.f / s;
    #pragma unroll
    for (int i = 0; i < 8; i++) out[OFF_ATT2 + b*T_ + tid + i*256] = e[i] * inv;
}

// -------- K3: agg2[b,d] = sum_t att2[b,t] * H[b,t,d] --------
__global__ void agg2_kernel(const float* __restrict__ H, const float* __restrict__ out){
    int b = blockIdx.y;
    int d = blockIdx.x * 128 + threadIdx.x;
    const float* a2 = out + OFF_ATT2 + b*T_;
    const float* Hb = H + (size_t)b * T_ * D_ + d;
    float acc = 0.f;
    for (int t = 0; t < T_; t += 8) {
        #pragma unroll
        for (int u = 0; u < 8; u++) acc += a2[t + u] * Hb[(size_t)(t + u) * D_];
    }
    g_agg2[b*D_ + d] = acc;
}

// -------- K4: G[:, 3D:4D] = H .* agg2 (broadcast over t) --------
__global__ void g4_kernel(const float* __restrict__ H, float* __restrict__ out){
    int idx = blockIdx.x * 256 + threadIdx.x;     // float4 index, < 8388608
    int d4 = idx & 255;
    int bt = idx >> 8;
    int b  = bt >> 11;
    float4 h = ((const float4*)H)[idx];
    float4 a = ((const float4*)g_agg2)[b*256 + d4];
    float4 r = make_float4(h.x*a.x, h.y*a.y, h.z*a.z, h.w*a.w);
    *(float4*)(out + OFF_G + (size_t)bt*4096 + 3072 + d4*4) = r;
}

extern "C" void kernel_launch(void* const* d_in, const int* in_sizes, int n_in,
                              void* d_out, int out_size){
    const float* H    = (const float*)d_in[0];
    const float* U    = (const float*)d_in[1];
    const float* w    = (const float*)d_in[2];
    const float* bias = (const float*)d_in[3];
    float* out = (float*)d_out;

    cudaFuncSetAttribute(fused1_kernel, cudaFuncAttributeMaxDynamicSharedMemorySize, SMEM1);

    colterm_kernel<<<256, 256>>>(U, w, bias);
    fused1_kernel<<<dim3(T_/64, B_), 256, SMEM1>>>(H, U, w, out);
    att2_kernel<<<B_, 256>>>(out);
    agg2_kernel<<<dim3(D_/128, B_), 128>>>(H, out);
    g4_kernel<<<(B_*T_*D_/4)/256, 256>>>(H, out);
}

// round 2
// speedup vs baseline: 1.3378x; 1.3378x over previous
#include <cuda_runtime.h>

#define B_ 16
#define T_ 2048
#define J_ 128
#define D_ 1024

#define N_ATT1 (B_*T_*J_)            // 4194304
#define OFF_ATT2 N_ATT1
#define N_ATT2 (B_*T_)               // 32768
#define OFF_G (OFF_ATT2 + N_ATT2)    // 4227072

#define SCOL 132
#define HST  36
#define SMEM1 ((64*SCOL + 128*SCOL + 128 + 64) * 4)   // 102144 bytes

#define TCH 32                        // t-chunks for agg2 partial reduction

__device__ float g_colterm[B_*J_];
__device__ float g_rowmax[B_*T_];
__device__ float g_agg2[B_*D_];
__device__ float g_agg2p[B_*TCH*D_];  // 2 MB partials

__device__ __forceinline__ unsigned f2tf32(float x){
    unsigned y; asm("cvt.rna.tf32.f32 %0, %1;" : "=r"(y) : "f"(x)); return y;
}

__device__ __forceinline__ void mma_tf32(float c[4], unsigned a0, unsigned a1, unsigned a2, unsigned a3,
                                         unsigned b0, unsigned b1){
    asm volatile("mma.sync.aligned.m16n8k8.row.col.f32.tf32.tf32.f32 "
        "{%0,%1,%2,%3}, {%4,%5,%6,%7}, {%8,%9}, {%0,%1,%2,%3};"
        : "+f"(c[0]), "+f"(c[1]), "+f"(c[2]), "+f"(c[3])
        : "r"(a0), "r"(a1), "r"(a2), "r"(a3), "r"(b0), "r"(b1));
}

// -------- K0: colterm[b,j] = U[b,j]·w2 + bias --------
__global__ void colterm_kernel(const float* __restrict__ U, const float* __restrict__ w,
                               const float* __restrict__ bias){
    int pair = blockIdx.x * 8 + (threadIdx.x >> 5);
    int lane = threadIdx.x & 31;
    const float* u  = U + (size_t)pair * D_;
    const float* w2 = w + D_;
    float s = 0.f;
    for (int k = lane; k < D_; k += 32) s += u[k] * w2[k];
    #pragma unroll
    for (int o = 16; o; o >>= 1) s += __shfl_xor_sync(0xffffffffu, s, o);
    if (lane == 0) g_colterm[pair] = s + bias[0];
}

// -------- K1: fused scores(tf32 mma) + softmax + agg1(tf32 mma) --------
__global__ __launch_bounds__(256, 2)
void fused1_kernel(const float* __restrict__ H, const float* __restrict__ U,
                   const float* __restrict__ w, float* __restrict__ out){
    extern __shared__ char smem_raw[];
    float*    att1sm = (float*)smem_raw;                          // 64 x 132
    unsigned* dyn    = (unsigned*)(smem_raw + 64*SCOL*4);         // 128 x 132 (phase C: Uc)
    unsigned* Hc     = dyn;                                       // 64 x 36  (phase A)
    unsigned* Vc     = dyn + 64*HST;                              // 128 x 36 (phase A)
    unsigned* Uc     = dyn;
    float*    cts    = (float*)(smem_raw + (64*SCOL + 128*SCOL)*4); // 128
    float*    hrow   = cts + 128;                                 // 64

    int tid  = threadIdx.x;
    int b    = blockIdx.y;
    int t0   = blockIdx.x * 64;
    int warp = tid >> 5, lane = tid & 31;
    int wm = warp >> 2, wn = warp & 3;
    int gid = lane >> 2, tig = lane & 3;

    if (tid < 128) cts[tid] = g_colterm[b*J_ + tid];

    const float* Hb = H + (size_t)(b*T_ + t0) * D_;
    const float* Ub = U + (size_t)b * J_ * D_;
    const float* w3 = w + 2*D_;
    float* Gb = out + OFF_G + (size_t)(b*T_ + t0) * 4096;

    float cacc[2][4][4];
    #pragma unroll
    for (int i = 0; i < 2; i++)
        #pragma unroll
        for (int j = 0; j < 4; j++)
            #pragma unroll
            for (int k = 0; k < 4; k++) cacc[i][j][k] = 0.f;

    float hp = 0.f;
    int hrow_r = tid >> 2, hpart = tid & 3;

    // ---- Phase A: S = (H .* w3) @ U^T, K = 1024 in chunks of 32; fused H@w1; G1 = H copy ----
    for (int kc = 0; kc < D_; kc += 32) {
        #pragma unroll
        for (int i = 0; i < 2; i++) {                 // H tile 64x32
            int idx = tid + i*256;
            int r = idx >> 3, c4 = (idx & 7) * 4;
            float4 h4 = *(const float4*)(Hb + (size_t)r*D_ + kc + c4);
            *(float4*)(Gb + (size_t)r*4096 + kc + c4) = h4;      // exact H copy into G[:, :D]
            uint4 u; u.x = f2tf32(h4.x); u.y = f2tf32(h4.y); u.z = f2tf32(h4.z); u.w = f2tf32(h4.w);
            *(uint4*)(Hc + r*HST + c4) = u;
        }
        #pragma unroll
        for (int i = 0; i < 4; i++) {                 // V = U .* w3 tile 128x32
            int idx = tid + i*256;
            int r = idx >> 3, c4 = (idx & 7) * 4;
            float4 u4 = *(const float4*)(Ub + (size_t)r*D_ + kc + c4);
            float4 w4 = *(const float4*)(w3 + kc + c4);
            uint4 v; v.x = f2tf32(u4.x*w4.x); v.y = f2tf32(u4.y*w4.y);
            v.z = f2tf32(u4.z*w4.z); v.w = f2tf32(u4.w*w4.w);
            *(uint4*)(Vc + r*HST + c4) = v;
        }
        __syncthreads();

        {   // H @ w1 partials (4 threads per row, 8 cols each)
            const float* w1c = w + kc + hpart*8;
            const unsigned* hc = Hc + hrow_r*HST + hpart*8;
            #pragma unroll
            for (int c = 0; c < 8; c++) hp += __uint_as_float(hc[c]) * w1c[c];
        }

        #pragma unroll
        for (int kt = 0; kt < 4; kt++) {
            unsigned bq0[4], bq1[4];
            #pragma unroll
            for (int nt = 0; nt < 4; nt++) {
                int j = wn*32 + nt*8 + gid;
                bq0[nt] = Vc[j*HST + kt*8 + tig];
                bq1[nt] = Vc[j*HST + kt*8 + 4 + tig];
            }
            #pragma unroll
            for (int mt = 0; mt < 2; mt++) {
                int r = wm*32 + mt*16 + gid;
                unsigned a0 = Hc[r*HST + kt*8 + tig];
                unsigned a1 = Hc[(r+8)*HST + kt*8 + tig];
                unsigned a2 = Hc[r*HST + kt*8 + 4 + tig];
                unsigned a3 = Hc[(r+8)*HST + kt*8 + 4 + tig];
                #pragma unroll
                for (int nt = 0; nt < 4; nt++) mma_tf32(cacc[mt][nt], a0, a1, a2, a3, bq0[nt], bq1[nt]);
            }
        }
        __syncthreads();
    }

    hp += __shfl_xor_sync(0xffffffffu, hp, 1);
    hp += __shfl_xor_sync(0xffffffffu, hp, 2);
    if (hpart == 0) hrow[hrow_r] = hp;

    // scores (minus row-constant h1+: cancels in softmax over j) -> smem
    #pragma unroll
    for (int mt = 0; mt < 2; mt++) {
        int r = wm*32 + mt*16 + gid;
        #pragma unroll
        for (int nt = 0; nt < 4; nt++) {
            int col = wn*32 + nt*8 + 2*tig;
            att1sm[r*SCOL + col]         = cacc[mt][nt][0] + cts[col];
            att1sm[r*SCOL + col + 1]     = cacc[mt][nt][1] + cts[col+1];
            att1sm[(r+8)*SCOL + col]     = cacc[mt][nt][2] + cts[col];
            att1sm[(r+8)*SCOL + col + 1] = cacc[mt][nt][3] + cts[col+1];
        }
    }
    __syncthreads();

    // ---- softmax over j (warp w owns rows w*8..w*8+7) ----
    float* att1out = out + (size_t)(b*T_ + t0) * J_;
    #pragma unroll
    for (int rr = 0; rr < 8; rr++) {
        int r = warp*8 + rr;
        float v0 = att1sm[r*SCOL + lane];
        float v1 = att1sm[r*SCOL + lane + 32];
        float v2 = att1sm[r*SCOL + lane + 64];
        float v3 = att1sm[r*SCOL + lane + 96];
        float mx = fmaxf(fmaxf(v0, v1), fmaxf(v2, v3));
        #pragma unroll
        for (int o = 16; o; o >>= 1) mx = fmaxf(mx, __shfl_xor_sync(0xffffffffu, mx, o));
        float e0 = __expf(v0 - mx), e1 = __expf(v1 - mx), e2 = __expf(v2 - mx), e3 = __expf(v3 - mx);
        float s = e0 + e1 + e2 + e3;
        #pragma unroll
        for (int o = 16; o; o >>= 1) s += __shfl_xor_sync(0xffffffffu, s, o);
        float inv = 1.f / s;
        e0 *= inv; e1 *= inv; e2 *= inv; e3 *= inv;
        att1out[(size_t)r*J_ + lane]      = e0;
        att1out[(size_t)r*J_ + lane + 32] = e1;
        att1out[(size_t)r*J_ + lane + 64] = e2;
        att1out[(size_t)r*J_ + lane + 96] = e3;
        att1sm[r*SCOL + lane]      = __uint_as_float(f2tf32(e0));   // stage tf32 att1 for GEMM2
        att1sm[r*SCOL + lane + 32] = __uint_as_float(f2tf32(e1));
        att1sm[r*SCOL + lane + 64] = __uint_as_float(f2tf32(e2));
        att1sm[r*SCOL + lane + 96] = __uint_as_float(f2tf32(e3));
        if (lane == 0) g_rowmax[b*T_ + t0 + r] = mx + hrow[r];      // full-score rowmax (bias in cts)
    }
    __syncthreads();

    // ---- Phase C: agg1 = att1 @ U (K = 128), d in chunks of 128; write G2 = agg1, G3 = H.*agg1 ----
    for (int dc = 0; dc < D_; dc += 128) {
        #pragma unroll
        for (int i = 0; i < 16; i++) {
            int idx = tid + i*256;
            int r = idx >> 5, c4 = (idx & 31) * 4;
            float4 u4 = *(const float4*)(Ub + (size_t)r*D_ + dc + c4);
            uint4 v; v.x = f2tf32(u4.x); v.y = f2tf32(u4.y); v.z = f2tf32(u4.z); v.w = f2tf32(u4.w);
            *(uint4*)(Uc + r*SCOL + c4) = v;
        }
        __syncthreads();

        float acc[2][4][4];
        #pragma unroll
        for (int i = 0; i < 2; i++)
            #pragma unroll
            for (int j = 0; j < 4; j++)
                #pragma unroll
                for (int k = 0; k < 4; k++) acc[i][j][k] = 0.f;

        #pragma unroll
        for (int kt = 0; kt < 16; kt++) {
            unsigned bq0[4], bq1[4];
            #pragma unroll
            for (int nt = 0; nt < 4; nt++) {
                int n = wn*32 + nt*8 + gid;
                bq0[nt] = Uc[(kt*8 + tig)*SCOL + n];
                bq1[nt] = Uc[(kt*8 + 4 + tig)*SCOL + n];
            }
            #pragma unroll
            for (int mt = 0; mt < 2; mt++) {
                int r = wm*32 + mt*16 + gid;
                unsigned a0 = __float_as_uint(att1sm[r*SCOL + kt*8 + tig]);
                unsigned a1 = __float_as_uint(att1sm[(r+8)*SCOL + kt*8 + tig]);
                unsigned a2 = __float_as_uint(att1sm[r*SCOL + kt*8 + 4 + tig]);
                unsigned a3 = __float_as_uint(att1sm[(r+8)*SCOL + kt*8 + 4 + tig]);
                #pragma unroll
                for (int nt = 0; nt < 4; nt++) mma_tf32(acc[mt][nt], a0, a1, a2, a3, bq0[nt], bq1[nt]);
            }
        }

        #pragma unroll
        for (int mt = 0; mt < 2; mt++) {
            #pragma unroll
            for (int nt = 0; nt < 4; nt++) {
                int r   = wm*32 + mt*16 + gid;
                int col = dc + wn*32 + nt*8 + 2*tig;
                float2 ha = *(const float2*)(Hb + (size_t)r*D_ + col);
                float2 hb = *(const float2*)(Hb + (size_t)(r+8)*D_ + col);
                float* g1 = Gb + (size_t)r*4096;
                float* g2 = Gb + (size_t)(r+8)*4096;
                *(float2*)(g1 + 1024 + col) = make_float2(acc[mt][nt][0], acc[mt][nt][1]);
                *(float2*)(g1 + 2048 + col) = make_float2(acc[mt][nt][0]*ha.x, acc[mt][nt][1]*ha.y);
                *(float2*)(g2 + 1024 + col) = make_float2(acc[mt][nt][2], acc[mt][nt][3]);
                *(float2*)(g2 + 2048 + col) = make_float2(acc[mt][nt][2]*hb.x, acc[mt][nt][3]*hb.y);
            }
        }
        __syncthreads();
    }
}

// -------- K2: att2[b,:] = softmax_t(rowmax[b,:]) --------
__global__ void att2_kernel(float* __restrict__ out){
    __shared__ float red[8];
    int b = blockIdx.x, tid = threadIdx.x;
    float v[8];
    #pragma unroll
    for (int i = 0; i < 8; i++) v[i] = g_rowmax[b*T_ + tid + i*256];
    float mx = v[0];
    #pragma unroll
    for (int i = 1; i < 8; i++) mx = fmaxf(mx, v[i]);
    #pragma unroll
    for (int o = 16; o; o >>= 1) mx = fmaxf(mx, __shfl_xor_sync(0xffffffffu, mx, o));
    if ((tid & 31) == 0) red[tid >> 5] = mx;
    __syncthreads();
    mx = red[0];
    #pragma unroll
    for (int i = 1; i < 8; i++) mx = fmaxf(mx, red[i]);
    float e[8], s = 0.f;
    #pragma unroll
    for (int i = 0; i < 8; i++) { e[i] = __expf(v[i] - mx); s += e[i]; }
    #pragma unroll
    for (int o = 16; o; o >>= 1) s += __shfl_xor_sync(0xffffffffu, s, o);
    __syncthreads();
    if ((tid & 31) == 0) red[tid >> 5] = s;
    __syncthreads();
    s = 0.f;
    #pragma unroll
    for (int i = 0; i < 8; i++) s += red[i];
    float inv = 1.f / s;
    #pragma unroll
    for (int i = 0; i < 8; i++) out[OFF_ATT2 + b*T_ + tid + i*256] = e[i] * inv;
}

// -------- K3a: partial agg2 over t-chunks (high parallelism, MLP=8) --------
__global__ __launch_bounds__(128)
void agg2p_kernel(const float* __restrict__ H, const float* __restrict__ out){
    int b  = blockIdx.z;
    int tc = blockIdx.y;                       // t-chunk, 64 rows each
    int d  = blockIdx.x * 128 + threadIdx.x;
    int t0 = tc * (T_/TCH);
    const float* a2 = out + OFF_ATT2 + b*T_ + t0;
    const float* Hb = H + ((size_t)b*T_ + t0) * D_ + d;
    float acc = 0.f;
    #pragma unroll 1
    for (int t = 0; t < T_/TCH; t += 8) {
        float p0 = a2[t+0] * Hb[(size_t)(t+0)*D_];
        float p1 = a2[t+1] * Hb[(size_t)(t+1)*D_];
        float p2 = a2[t+2] * Hb[(size_t)(t+2)*D_];
        float p3 = a2[t+3] * Hb[(size_t)(t+3)*D_];
        float p4 = a2[t+4] * Hb[(size_t)(t+4)*D_];
        float p5 = a2[t+5] * Hb[(size_t)(t+5)*D_];
        float p6 = a2[t+6] * Hb[(size_t)(t+6)*D_];
        float p7 = a2[t+7] * Hb[(size_t)(t+7)*D_];
        acc += ((p0+p1)+(p2+p3)) + ((p4+p5)+(p6+p7));
    }
    g_agg2p[((size_t)b*TCH + tc)*D_ + d] = acc;
}

// -------- K3b: reduce partials --------
__global__ void agg2r_kernel(){
    int idx = blockIdx.x * 256 + threadIdx.x;   // < B_*D_ = 16384
    int b = idx >> 10, d = idx & 1023;
    const float* p = g_agg2p + (size_t)b*TCH*D_ + d;
    float acc = 0.f;
    #pragma unroll
    for (int c = 0; c < TCH; c++) acc += p[(size_t)c*D_];
    g_agg2[idx] = acc;
}

// -------- K4: G[:, 3D:4D] = H .* agg2 (broadcast over t) --------
__global__ void g4_kernel(const float* __restrict__ H, float* __restrict__ out){
    int idx = blockIdx.x * 256 + threadIdx.x;     // float4 index, < 8388608
    int d4 = idx & 255;
    int bt = idx >> 8;
    int b  = bt >> 11;
    float4 h = ((const float4*)H)[idx];
    float4 a = ((const float4*)g_agg2)[b*256 + d4];
    float4 r = make_float4(h.x*a.x, h.y*a.y, h.z*a.z, h.w*a.w);
    *(float4*)(out + OFF_G + (size_t)bt*4096 + 3072 + d4*4) = r;
}

extern "C" void kernel_launch(void* const* d_in, const int* in_sizes, int n_in,
                              void* d_out, int out_size){
    const float* H    = (const float*)d_in[0];
    const float* U    = (const float*)d_in[1];
    const float* w    = (const float*)d_in[2];
    const float* bias = (const float*)d_in[3];
    float* out = (float*)d_out;

    cudaFuncSetAttribute(fused1_kernel, cudaFuncAttributeMaxDynamicSharedMemorySize, SMEM1);

    colterm_kernel<<<256, 256>>>(U, w, bias);
    fused1_kernel<<<dim3(T_/64, B_), 256, SMEM1>>>(H, U, w, out);
    att2_kernel<<<B_, 256>>>(out);
    agg2p_kernel<<<dim3(D_/128, TCH, B_), 128>>>(H, out);
    agg2r_kernel<<<B_*D_/256, 256>>>();
    g4_kernel<<<(B_*T_*D_/4)/256, 256>>>(H, out);
}

// round 3
// speedup vs baseline: 1.4921x; 1.1153x over previous
#include <cuda_runtime.h>

#define B_ 16
#define T_ 2048
#define J_ 128
#define D_ 1024

#define N_ATT1 (B_*T_*J_)            // 4194304
#define OFF_ATT2 N_ATT1
#define N_ATT2 (B_*T_)               // 32768
#define OFF_G (OFF_ATT2 + N_ATT2)    // 4227072

#define SCOL 132                      // att1sm row stride
#define HST  36                       // phase A tile stride
#define UST  72                       // phase C U tile stride (bank offset 8 -> conflict-free)
#define DYNF 18432                    // floats in the double-buffer region (phase C: 2*128*72)
#define SMEM1 ((64*SCOL + DYNF + 128 + 64) * 4)   // 108288 bytes

#define TCH 32                        // t-chunks for agg2 partial reduction

__device__ float g_colterm[B_*J_];
__device__ float g_rowmax[B_*T_];
__device__ float g_agg2[B_*D_];
__device__ float g_agg2p[B_*TCH*D_];
__device__ float g_uw3[B_*J_*D_];     // U .* w3 (8 MB)

__device__ __forceinline__ void cp16(void* smem, const void* g){
    unsigned s = (unsigned)__cvta_generic_to_shared(smem);
    asm volatile("cp.async.cg.shared.global [%0], [%1], 16;" :: "r"(s), "l"(g));
}
#define CP_COMMIT asm volatile("cp.async.commit_group;")
#define CP_WAIT1  asm volatile("cp.async.wait_group 1;")
#define CP_WAIT0  asm volatile("cp.async.wait_group 0;")

__device__ __forceinline__ void mma_tf32(float c[4], unsigned a0, unsigned a1, unsigned a2, unsigned a3,
                                         unsigned b0, unsigned b1){
    asm volatile("mma.sync.aligned.m16n8k8.row.col.f32.tf32.tf32.f32 "
        "{%0,%1,%2,%3}, {%4,%5,%6,%7}, {%8,%9}, {%0,%1,%2,%3};"
        : "+f"(c[0]), "+f"(c[1]), "+f"(c[2]), "+f"(c[3])
        : "r"(a0), "r"(a1), "r"(a2), "r"(a3), "r"(b0), "r"(b1));
}

// -------- K0a: colterm[b,j] = U[b,j]·w2 + bias --------
__global__ void colterm_kernel(const float* __restrict__ U, const float* __restrict__ w,
                               const float* __restrict__ bias){
    int pair = blockIdx.x * 8 + (threadIdx.x >> 5);
    int lane = threadIdx.x & 31;
    const float* u  = U + (size_t)pair * D_;
    const float* w2 = w + D_;
    float s = 0.f;
    for (int k = lane; k < D_; k += 32) s += u[k] * w2[k];
    #pragma unroll
    for (int o = 16; o; o >>= 1) s += __shfl_xor_sync(0xffffffffu, s, o);
    if (lane == 0) g_colterm[pair] = s + bias[0];
}

// -------- K0b: g_uw3 = U .* w3 --------
__global__ void uw3_kernel(const float* __restrict__ U, const float* __restrict__ w){
    int idx = blockIdx.x * 256 + threadIdx.x;   // float4 idx < 524288
    int d4 = idx & 255;
    float4 u = ((const float4*)U)[idx];
    float4 w3 = *(const float4*)(w + 2*D_ + d4*4);
    ((float4*)g_uw3)[idx] = make_float4(u.x*w3.x, u.y*w3.y, u.z*w3.z, u.w*w3.w);
}

// -------- K1: fused scores + softmax + agg1 (cp.async pipelined, tf32 mma) --------
__global__ __launch_bounds__(256, 2)
void fused1_kernel(const float* __restrict__ H, const float* __restrict__ U,
                   const float* __restrict__ w, float* __restrict__ out){
    extern __shared__ char smem_raw[];
    float* att1sm = (float*)smem_raw;                // 64 x 132
    float* dyn    = att1sm + 64*SCOL;                // 18432 floats, double-buffer region
    float* cts    = dyn + DYNF;                      // 128
    float* hrow   = cts + 128;                       // 64

    int tid  = threadIdx.x;
    int b    = blockIdx.y;
    int t0   = blockIdx.x * 64;
    int warp = tid >> 5, lane = tid & 31;
    int wm = warp >> 2, wn = warp & 3;
    int gid = lane >> 2, tig = lane & 3;

    if (tid < 128) cts[tid] = g_colterm[b*J_ + tid];

    const float* Hb = H + (size_t)(b*T_ + t0) * D_;
    const float* Ub = U + (size_t)b * J_ * D_;
    const float* UW = g_uw3 + (size_t)b * J_ * D_;
    float* Gb = out + OFF_G + (size_t)(b*T_ + t0) * 4096;

    float cacc[2][4][4];
    #pragma unroll
    for (int i = 0; i < 2; i++)
        #pragma unroll
        for (int j = 0; j < 4; j++)
            #pragma unroll
            for (int k = 0; k < 4; k++) cacc[i][j][k] = 0.f;

    float hp = 0.f;
    int hrow_r = tid >> 2, hpart = tid & 3;
    int lr = tid >> 3, lc4 = (tid & 7) * 4;          // phase A loader coords

    // ---- prefetch chunk 0 ----
    {
        float* Hs = dyn;  float* Vs = dyn + 64*HST;
        cp16(Hs + lr*HST + lc4,        Hb + (size_t)lr*D_ + lc4);
        cp16(Hs + (lr+32)*HST + lc4,   Hb + (size_t)(lr+32)*D_ + lc4);
        #pragma unroll
        for (int i = 0; i < 4; i++){
            int r = lr + i*32;
            cp16(Vs + r*HST + lc4, UW + (size_t)r*D_ + lc4);
        }
        CP_COMMIT;
    }

    // ---- Phase A: S = (H .* w3) @ U^T, K=1024, 32-wide chunks, double-buffered ----
    for (int kci = 0; kci < 32; kci++){
        int cur = kci & 1;
        if (kci < 31){
            int kc = (kci + 1) * 32;
            float* Hs = dyn + (cur^1)*192*HST;  float* Vs = Hs + 64*HST;
            cp16(Hs + lr*HST + lc4,      Hb + (size_t)lr*D_ + kc + lc4);
            cp16(Hs + (lr+32)*HST + lc4, Hb + (size_t)(lr+32)*D_ + kc + lc4);
            #pragma unroll
            for (int i = 0; i < 4; i++){
                int r = lr + i*32;
                cp16(Vs + r*HST + lc4, UW + (size_t)r*D_ + kc + lc4);
            }
            CP_COMMIT;
            CP_WAIT1;
        } else {
            CP_WAIT0;
        }
        __syncthreads();

        float* Hs = dyn + cur*192*HST;  float* Vs = Hs + 64*HST;

        {   // H @ w1 partials (4 threads per row, 8 cols each)
            const float* w1c = w + kci*32 + hpart*8;
            const float* hc = Hs + hrow_r*HST + hpart*8;
            #pragma unroll
            for (int c = 0; c < 8; c++) hp += hc[c] * w1c[c];
        }

        #pragma unroll
        for (int kt = 0; kt < 4; kt++){
            unsigned bq0[4], bq1[4];
            #pragma unroll
            for (int nt = 0; nt < 4; nt++){
                int j = wn*32 + nt*8 + gid;
                bq0[nt] = __float_as_uint(Vs[j*HST + kt*8 + tig]);
                bq1[nt] = __float_as_uint(Vs[j*HST + kt*8 + 4 + tig]);
            }
            #pragma unroll
            for (int mt = 0; mt < 2; mt++){
                int r = wm*32 + mt*16 + gid;
                unsigned a0 = __float_as_uint(Hs[r*HST + kt*8 + tig]);
                unsigned a1 = __float_as_uint(Hs[(r+8)*HST + kt*8 + tig]);
                unsigned a2 = __float_as_uint(Hs[r*HST + kt*8 + 4 + tig]);
                unsigned a3 = __float_as_uint(Hs[(r+8)*HST + kt*8 + 4 + tig]);
                #pragma unroll
                for (int nt = 0; nt < 4; nt++) mma_tf32(cacc[mt][nt], a0, a1, a2, a3, bq0[nt], bq1[nt]);
            }
        }
        __syncthreads();
    }

    // ---- prefetch phase C chunk 0 (overlaps epilogue + softmax) ----
    {
        float* Us = dyn;
        int r = tid >> 4, c4 = (tid & 15) * 4;
        #pragma unroll
        for (int i = 0; i < 8; i++)
            cp16(Us + (r + i*16)*UST + c4, Ub + (size_t)(r + i*16)*D_ + c4);
        CP_COMMIT;
    }

    hp += __shfl_xor_sync(0xffffffffu, hp, 1);
    hp += __shfl_xor_sync(0xffffffffu, hp, 2);
    if (hpart == 0) hrow[hrow_r] = hp;

    // scores (minus row-constant h1: cancels in softmax over j) -> smem
    #pragma unroll
    for (int mt = 0; mt < 2; mt++){
        int r = wm*32 + mt*16 + gid;
        #pragma unroll
        for (int nt = 0; nt < 4; nt++){
            int col = wn*32 + nt*8 + 2*tig;
            att1sm[r*SCOL + col]         = cacc[mt][nt][0] + cts[col];
            att1sm[r*SCOL + col + 1]     = cacc[mt][nt][1] + cts[col+1];
            att1sm[(r+8)*SCOL + col]     = cacc[mt][nt][2] + cts[col];
            att1sm[(r+8)*SCOL + col + 1] = cacc[mt][nt][3] + cts[col+1];
        }
    }
    __syncthreads();

    // ---- softmax over j (warp w owns rows w*8..w*8+7) ----
    float* att1out = out + (size_t)(b*T_ + t0) * J_;
    #pragma unroll
    for (int rr = 0; rr < 8; rr++){
        int r = warp*8 + rr;
        float v0 = att1sm[r*SCOL + lane];
        float v1 = att1sm[r*SCOL + lane + 32];
        float v2 = att1sm[r*SCOL + lane + 64];
        float v3 = att1sm[r*SCOL + lane + 96];
        float mx = fmaxf(fmaxf(v0, v1), fmaxf(v2, v3));
        #pragma unroll
        for (int o = 16; o; o >>= 1) mx = fmaxf(mx, __shfl_xor_sync(0xffffffffu, mx, o));
        float e0 = __expf(v0 - mx), e1 = __expf(v1 - mx), e2 = __expf(v2 - mx), e3 = __expf(v3 - mx);
        float s = e0 + e1 + e2 + e3;
        #pragma unroll
        for (int o = 16; o; o >>= 1) s += __shfl_xor_sync(0xffffffffu, s, o);
        float inv = 1.f / s;
        e0 *= inv; e1 *= inv; e2 *= inv; e3 *= inv;
        att1out[(size_t)r*J_ + lane]      = e0;
        att1out[(size_t)r*J_ + lane + 32] = e1;
        att1out[(size_t)r*J_ + lane + 64] = e2;
        att1out[(size_t)r*J_ + lane + 96] = e3;
        att1sm[r*SCOL + lane]      = e0;    // stage att1 for GEMM2 (raw fp32, HW truncates)
        att1sm[r*SCOL + lane + 32] = e1;
        att1sm[r*SCOL + lane + 64] = e2;
        att1sm[r*SCOL + lane + 96] = e3;
        if (lane == 0) g_rowmax[b*T_ + t0 + r] = mx + hrow[r];
    }

    // ---- Phase C: agg1 = att1 @ U, d in 64-col chunks, double-buffered ----
    int ur = tid >> 4, uc4 = (tid & 15) * 4;
    for (int c = 0; c < 16; c++){
        int cur = c & 1;
        if (c < 15){
            int dc = (c + 1) * 64;
            float* Us = dyn + (cur^1)*128*UST;
            #pragma unroll
            for (int i = 0; i < 8; i++)
                cp16(Us + (ur + i*16)*UST + uc4, Ub + (size_t)(ur + i*16)*D_ + dc + uc4);
            CP_COMMIT;
            CP_WAIT1;
        } else {
            CP_WAIT0;
        }
        __syncthreads();

        float* Us = dyn + cur*128*UST;
        float acc[2][2][4];
        #pragma unroll
        for (int i = 0; i < 2; i++)
            #pragma unroll
            for (int j = 0; j < 2; j++)
                #pragma unroll
                for (int k = 0; k < 4; k++) acc[i][j][k] = 0.f;

        #pragma unroll
        for (int kt = 0; kt < 16; kt++){
            unsigned bq0[2], bq1[2];
            #pragma unroll
            for (int nt = 0; nt < 2; nt++){
                int n = wn*16 + nt*8 + gid;
                bq0[nt] = __float_as_uint(Us[(kt*8 + tig)*UST + n]);
                bq1[nt] = __float_as_uint(Us[(kt*8 + 4 + tig)*UST + n]);
            }
            #pragma unroll
            for (int mt = 0; mt < 2; mt++){
                int r = wm*32 + mt*16 + gid;
                unsigned a0 = __float_as_uint(att1sm[r*SCOL + kt*8 + tig]);
                unsigned a1 = __float_as_uint(att1sm[(r+8)*SCOL + kt*8 + tig]);
                unsigned a2 = __float_as_uint(att1sm[r*SCOL + kt*8 + 4 + tig]);
                unsigned a3 = __float_as_uint(att1sm[(r+8)*SCOL + kt*8 + 4 + tig]);
                #pragma unroll
                for (int nt = 0; nt < 2; nt++) mma_tf32(acc[mt][nt], a0, a1, a2, a3, bq0[nt], bq1[nt]);
            }
        }

        int dc = c * 64;
        #pragma unroll
        for (int mt = 0; mt < 2; mt++){
            #pragma unroll
            for (int nt = 0; nt < 2; nt++){
                int r   = wm*32 + mt*16 + gid;
                int col = dc + wn*16 + nt*8 + 2*tig;
                float2 ha = *(const float2*)(Hb + (size_t)r*D_ + col);
                float2 hb2 = *(const float2*)(Hb + (size_t)(r+8)*D_ + col);
                float* g1 = Gb + (size_t)r*4096;
                float* g2 = Gb + (size_t)(r+8)*4096;
                *(float2*)(g1 + 1024 + col) = make_float2(acc[mt][nt][0], acc[mt][nt][1]);
                *(float2*)(g1 + 2048 + col) = make_float2(acc[mt][nt][0]*ha.x, acc[mt][nt][1]*ha.y);
                *(float2*)(g2 + 1024 + col) = make_float2(acc[mt][nt][2], acc[mt][nt][3]);
                *(float2*)(g2 + 2048 + col) = make_float2(acc[mt][nt][2]*hb2.x, acc[mt][nt][3]*hb2.y);
            }
        }
        __syncthreads();
    }
}

// -------- K2: att2[b,:] = softmax_t(rowmax[b,:]) --------
__global__ void att2_kernel(float* __restrict__ out){
    __shared__ float red[8];
    int b = blockIdx.x, tid = threadIdx.x;
    float v[8];
    #pragma unroll
    for (int i = 0; i < 8; i++) v[i] = g_rowmax[b*T_ + tid + i*256];
    float mx = v[0];
    #pragma unroll
    for (int i = 1; i < 8; i++) mx = fmaxf(mx, v[i]);
    #pragma unroll
    for (int o = 16; o; o >>= 1) mx = fmaxf(mx, __shfl_xor_sync(0xffffffffu, mx, o));
    if ((tid & 31) == 0) red[tid >> 5] = mx;
    __syncthreads();
    mx = red[0];
    #pragma unroll
    for (int i = 1; i < 8; i++) mx = fmaxf(mx, red[i]);
    float e[8], s = 0.f;
    #pragma unroll
    for (int i = 0; i < 8; i++) { e[i] = __expf(v[i] - mx); s += e[i]; }
    #pragma unroll
    for (int o = 16; o; o >>= 1) s += __shfl_xor_sync(0xffffffffu, s, o);
    __syncthreads();
    if ((tid & 31) == 0) red[tid >> 5] = s;
    __syncthreads();
    s = 0.f;
    #pragma unroll
    for (int i = 0; i < 8; i++) s += red[i];
    float inv = 1.f / s;
    #pragma unroll
    for (int i = 0; i < 8; i++) out[OFF_ATT2 + b*T_ + tid + i*256] = e[i] * inv;
}

// -------- K3a: partial agg2 over t-chunks (float4, MLP=8) --------
__global__ __launch_bounds__(128)
void agg2p_kernel(const float* __restrict__ H, const float* __restrict__ out){
    int b  = blockIdx.z;
    int tc = blockIdx.y;
    int d4 = blockIdx.x * 128 + threadIdx.x;   // float4 column index, < 256
    int t0 = tc * (T_/TCH);
    const float* a2 = out + OFF_ATT2 + b*T_ + t0;
    const float4* Hb = (const float4*)(H + ((size_t)b*T_ + t0) * D_) + d4;
    float4 acc = make_float4(0.f, 0.f, 0.f, 0.f);
    #pragma unroll 1
    for (int t = 0; t < T_/TCH; t += 8) {
        #pragma unroll
        for (int u = 0; u < 8; u++){
            float a = a2[t+u];
            float4 h = Hb[(size_t)(t+u) * 256];
            acc.x += a*h.x; acc.y += a*h.y; acc.z += a*h.z; acc.w += a*h.w;
        }
    }
    ((float4*)g_agg2p)[((size_t)b*TCH + tc)*256 + d4] = acc;
}

// -------- K3b: reduce partials --------
__global__ void agg2r_kernel(){
    int idx = blockIdx.x * 256 + threadIdx.x;   // < B_*D_ = 16384
    int b = idx >> 10, d = idx & 1023;
    const float* p = g_agg2p + (size_t)b*TCH*D_ + d;
    float acc = 0.f;
    #pragma unroll
    for (int c = 0; c < TCH; c++) acc += p[(size_t)c*D_];
    g_agg2[idx] = acc;
}

// -------- K4: G[:, 0:D] = H ; G[:, 3D:4D] = H .* agg2 --------
__global__ void g45_kernel(const float* __restrict__ H, float* __restrict__ out){
    int idx = blockIdx.x * 256 + threadIdx.x;     // float4 index, < 8388608
    int d4 = idx & 255;
    int bt = idx >> 8;
    int b  = bt >> 11;
    float4 h = ((const float4*)H)[idx];
    float4 a = ((const float4*)g_agg2)[b*256 + d4];
    float* Gb = out + OFF_G + (size_t)bt*4096;
    *(float4*)(Gb + d4*4) = h;
    *(float4*)(Gb + 3072 + d4*4) = make_float4(h.x*a.x, h.y*a.y, h.z*a.z, h.w*a.w);
}

extern "C" void kernel_launch(void* const* d_in, const int* in_sizes, int n_in,
                              void* d_out, int out_size){
    const float* H    = (const float*)d_in[0];
    const float* U    = (const float*)d_in[1];
    const float* w    = (const float*)d_in[2];
    const float* bias = (const float*)d_in[3];
    float* out = (float*)d_out;

    cudaFuncSetAttribute(fused1_kernel, cudaFuncAttributeMaxDynamicSharedMemorySize, SMEM1);

    colterm_kernel<<<256, 256>>>(U, w, bias);
    uw3_kernel<<<B_*J_*D_/4/256, 256>>>(U, w);
    fused1_kernel<<<dim3(T_/64, B_), 256, SMEM1>>>(H, U, w, out);
    att2_kernel<<<B_, 256>>>(out);
    agg2p_kernel<<<dim3(2, TCH, B_), 128>>>(H, out);
    agg2r_kernel<<<B_*D_/256, 256>>>();
    g45_kernel<<<(B_*T_*D_/4)/256, 256>>>(H, out);
}